// round 5
// baseline (speedup 1.0000x reference)
#include <cuda_runtime.h>
#include <cuda_bf16.h>
#include <cstdint>

#define N_NODES 100000
#define N_EDGES 3200000
#define NFEAT 1433
#define NHID 40
#define NCLASS 7
#define NC_PAD 8   // padded class dim for vectorized reds

// ---------------- scratch (device globals; no allocations allowed) -------------
__device__ __align__(16) float g_support1[N_NODES * NHID];   // x @ W1
__device__ __align__(16) float g_agg1[N_NODES * NHID];       // scatter target 1
__device__ __align__(16) float g_support2[N_NODES * NC_PAD]; // h @ W2 (padded)
__device__ __align__(16) float g_agg2[N_NODES * NC_PAD];     // scatter target 2

// ---------------- f32x2 helpers (sm_100+ packed fp32) -------------------------
__device__ __forceinline__ void ffma2(unsigned long long& d,
                                      unsigned long long a,
                                      unsigned long long b) {
    asm("fma.rn.f32x2 %0, %1, %2, %0;" : "+l"(d) : "l"(a), "l"(b));
}
__device__ __forceinline__ float2 unpack_f32x2(unsigned long long p) {
    float2 r;
    asm("mov.b64 {%0, %1}, %2;" : "=f"(r.x), "=f"(r.y) : "l"(p));
    return r;
}

// vector fp32 reduction (sm_90+): one RED.128 instead of 4 scalar REDs
__device__ __forceinline__ void red_add_v4(float* addr, float4 v) {
    asm volatile("red.global.add.v4.f32 [%0], {%1, %2, %3, %4};"
                 :: "l"(addr), "f"(v.x), "f"(v.y), "f"(v.z), "f"(v.w)
                 : "memory");
}

// cp.async 4B with zero-fill predication (src-size 0 => writes zeros)
__device__ __forceinline__ void cp_async4(unsigned int smem_addr, const void* gptr, bool pred) {
    int bytes = pred ? 4 : 0;
    asm volatile("cp.async.ca.shared.global [%0], [%1], 4, %2;"
                 :: "r"(smem_addr), "l"(gptr), "r"(bytes));
}
__device__ __forceinline__ void cp_async_commit() {
    asm volatile("cp.async.commit_group;");
}
template <int N>
__device__ __forceinline__ void cp_async_wait() {
    asm volatile("cp.async.wait_group %0;" :: "n"(N));
}

// ---------------- GEMM1: support1 = x @ W1  (N x 1433 @ 1433 x 40) ------------
// 256 threads, 256-row x 40-col block tile, thread tile 4 rows x 10 cols.
// K-split f32x2: each FFMA2 does 2 consecutive k-steps (lo=even k, hi=odd k);
// halves summed in epilogue. cp.async double-buffered KC=16 pipeline.
#define G1_KC 16
#define G1_NCH ((NFEAT + G1_KC - 1) / G1_KC)  // 90
#define SX_STRIDE 18
#define SW_STRIDE 18

__device__ __forceinline__ void g1_load_chunk(float* sxb, float* swb,
                                              const float* __restrict__ x,
                                              const float* __restrict__ W1,
                                              int row0, int kb, int tid) {
    // x tile: 256 rows x 16 k = 4096 elems, 16 per thread (k-fastest, coalesced)
#pragma unroll
    for (int i = 0; i < 16; i++) {
        int idx = tid + i * 256;
        int kk = idx & 15;
        int r = idx >> 4;
        int gr = row0 + r;
        int gk = kb + kk;
        bool p = (gr < N_NODES) && (gk < NFEAT);
        const float* gsrc = p ? (x + (long long)gr * NFEAT + gk) : x;
        unsigned int dst = (unsigned int)__cvta_generic_to_shared(sxb + r * SX_STRIDE + kk);
        cp_async4(dst, gsrc, p);
    }
    // W tile: 16 k x 40 c = 640 elems, linear read (coalesced), store [c][kk]
#pragma unroll
    for (int i = 0; i < 3; i++) {
        int idx = tid + i * 256;
        if (idx < G1_KC * NHID) {
            int kk = idx / NHID;
            int c = idx - kk * NHID;
            bool p = (kb + kk) < NFEAT;
            const float* gsrc = p ? (W1 + (long long)(kb + kk) * NHID + c) : W1;
            unsigned int dst = (unsigned int)__cvta_generic_to_shared(swb + c * SW_STRIDE + kk);
            cp_async4(dst, gsrc, p);
        }
    }
}

__global__ __launch_bounds__(256, 2) void gemm1_kernel(const float* __restrict__ x,
                                                       const float* __restrict__ W1) {
    __shared__ float sx[2][256 * SX_STRIDE];
    __shared__ float sw[2][NHID * SW_STRIDE];

    const int tid = threadIdx.x;
    const int cg = tid & 3;          // col group: 10 cols
    const int rt = tid >> 2;         // row group: 4 rows (0..63)
    const int c0 = cg * 10;
    const int row0 = blockIdx.x * 256;

    unsigned long long acc[4][10];
#pragma unroll
    for (int i = 0; i < 4; i++)
#pragma unroll
        for (int j = 0; j < 10; j++) acc[i][j] = 0ull;

    g1_load_chunk(sx[0], sw[0], x, W1, row0, 0, tid);
    cp_async_commit();

    int cur = 0;
    for (int c = 0; c < G1_NCH; c++) {
        if (c + 1 < G1_NCH) {
            g1_load_chunk(sx[cur ^ 1], sw[cur ^ 1], x, W1, row0, (c + 1) * G1_KC, tid);
            cp_async_commit();
            cp_async_wait<1>();
        } else {
            cp_async_wait<0>();
        }
        __syncthreads();

        const float* sxb = sx[cur];
        const float* swb = sw[cur];
#pragma unroll
        for (int kp = 0; kp < G1_KC / 2; kp++) {
            unsigned long long wv[10], xv[4];
#pragma unroll
            for (int j = 0; j < 10; j++)
                wv[j] = *reinterpret_cast<const unsigned long long*>(
                    swb + (c0 + j) * SW_STRIDE + 2 * kp);
#pragma unroll
            for (int i = 0; i < 4; i++)
                xv[i] = *reinterpret_cast<const unsigned long long*>(
                    sxb + (rt * 4 + i) * SX_STRIDE + 2 * kp);
#pragma unroll
            for (int i = 0; i < 4; i++)
#pragma unroll
                for (int j = 0; j < 10; j++) ffma2(acc[i][j], xv[i], wv[j]);
        }
        __syncthreads();
        cur ^= 1;
    }

    // epilogue: sum the two k-halves, store as float2 pairs
#pragma unroll
    for (int i = 0; i < 4; i++) {
        int gr = row0 + rt * 4 + i;
        if (gr < N_NODES) {
#pragma unroll
            for (int j = 0; j < 5; j++) {
                float2 a = unpack_f32x2(acc[i][2 * j]);
                float2 b = unpack_f32x2(acc[i][2 * j + 1]);
                float2 v = make_float2(a.x + a.y, b.x + b.y);
                *reinterpret_cast<float2*>(&g_support1[gr * NHID + c0 + 2 * j]) = v;
            }
        }
    }
}

// ---------------- zero both scatter targets ------------------------------------
__global__ void zero_kernel() {
    int i = blockIdx.x * blockDim.x + threadIdx.x;
    const int n1 = N_NODES * NHID / 4;
    const int n2 = N_NODES * NC_PAD / 4;
    if (i < n1)
        reinterpret_cast<float4*>(g_agg1)[i] = make_float4(0.f, 0.f, 0.f, 0.f);
    else if (i < n1 + n2)
        reinterpret_cast<float4*>(g_agg2)[i - n1] = make_float4(0.f, 0.f, 0.f, 0.f);
}

// ---------------- scatter 1: agg1[dst] += support1[src] * w  (40 wide) ---------
__global__ __launch_bounds__(256) void scatter1_kernel(const int* __restrict__ src,
                                                       const int* __restrict__ dst,
                                                       const float* __restrict__ ew) {
    int t = blockIdx.x * blockDim.x + threadIdx.x;
    if (t >= N_EDGES * 10) return;
    int e = t / 10;
    int c = t - e * 10;           // chunk 0..9
    int s = src[e];
    int d = dst[e];
    float w = ew[e];
    float4 v = reinterpret_cast<const float4*>(g_support1 + s * NHID)[c];
    v.x *= w; v.y *= w; v.z *= w; v.w *= w;
    red_add_v4(g_agg1 + d * NHID + c * 4, v);
}

// ---------------- layer-1 epilogue fused with GEMM2 ----------------------------
__global__ __launch_bounds__(256) void mid_kernel(const float* __restrict__ b1,
                                                  const float* __restrict__ W2,
                                                  const float* __restrict__ mask) {
    __shared__ float sW2[NHID][NCLASS];
    __shared__ float sb1[NHID];
    int tid = threadIdx.x;
    for (int i = tid; i < NHID * NCLASS; i += blockDim.x)
        sW2[i / NCLASS][i % NCLASS] = W2[i];
    if (tid < NHID) sb1[tid] = b1[tid];
    __syncthreads();

    int n = blockIdx.x * blockDim.x + tid;
    if (n >= N_NODES) return;

    float acc[NC_PAD];
#pragma unroll
    for (int c = 0; c < NC_PAD; c++) acc[c] = 0.f;

    const float4* arow = reinterpret_cast<const float4*>(g_agg1 + n * NHID);
    const float4* mrow = reinterpret_cast<const float4*>(mask + n * NHID);
#pragma unroll
    for (int q = 0; q < NHID / 4; q++) {
        float4 a = arow[q];
        float4 m = mrow[q];
        float hv[4];
        hv[0] = (m.x > 0.5f) ? fmaxf(a.x + sb1[4 * q + 0], 0.f) * 2.f : 0.f;
        hv[1] = (m.y > 0.5f) ? fmaxf(a.y + sb1[4 * q + 1], 0.f) * 2.f : 0.f;
        hv[2] = (m.z > 0.5f) ? fmaxf(a.z + sb1[4 * q + 2], 0.f) * 2.f : 0.f;
        hv[3] = (m.w > 0.5f) ? fmaxf(a.w + sb1[4 * q + 3], 0.f) * 2.f : 0.f;
#pragma unroll
        for (int u = 0; u < 4; u++) {
#pragma unroll
            for (int c = 0; c < NCLASS; c++) acc[c] += hv[u] * sW2[4 * q + u][c];
        }
    }
    float4* orow = reinterpret_cast<float4*>(g_support2 + n * NC_PAD);
    orow[0] = make_float4(acc[0], acc[1], acc[2], acc[3]);
    orow[1] = make_float4(acc[4], acc[5], acc[6], 0.f);
}

// ---------------- scatter 2: agg2[dst] += support2[src] * w  (8 wide padded) ---
__global__ __launch_bounds__(256) void scatter2_kernel(const int* __restrict__ src,
                                                       const int* __restrict__ dst,
                                                       const float* __restrict__ ew) {
    int t = blockIdx.x * blockDim.x + threadIdx.x;
    if (t >= N_EDGES * 2) return;
    int e = t >> 1;
    int c = t & 1;
    int s = src[e];
    int d = dst[e];
    float w = ew[e];
    float4 v = reinterpret_cast<const float4*>(g_support2 + s * NC_PAD)[c];
    v.x *= w; v.y *= w; v.z *= w; v.w *= w;
    red_add_v4(g_agg2 + d * NC_PAD + c * 4, v);
}

// ---------------- final: out = log_softmax(agg2 + b2) --------------------------
__global__ __launch_bounds__(256) void logsoftmax_kernel(const float* __restrict__ b2,
                                                         float* __restrict__ out) {
    int n = blockIdx.x * blockDim.x + threadIdx.x;
    if (n >= N_NODES) return;
    float v[NCLASS];
    float m = -1e30f;
#pragma unroll
    for (int c = 0; c < NCLASS; c++) {
        v[c] = g_agg2[n * NC_PAD + c] + b2[c];
        m = fmaxf(m, v[c]);
    }
    float sum = 0.f;
#pragma unroll
    for (int c = 0; c < NCLASS; c++) sum += expf(v[c] - m);
    float l = m + logf(sum);
#pragma unroll
    for (int c = 0; c < NCLASS; c++) out[n * NCLASS + c] = v[c] - l;
}

// ---------------- launch --------------------------------------------------------
extern "C" void kernel_launch(void* const* d_in, const int* in_sizes, int n_in,
                              void* d_out, int out_size) {
    const float* x    = (const float*)d_in[0];
    const int*   src  = (const int*)d_in[1];
    const int*   dst  = (const int*)d_in[2];
    const float* ew   = (const float*)d_in[3];
    const float* W1   = (const float*)d_in[4];
    const float* b1   = (const float*)d_in[5];
    const float* W2   = (const float*)d_in[6];
    const float* b2   = (const float*)d_in[7];
    const float* mask = (const float*)d_in[8];
    float* out = (float*)d_out;

    (void)in_sizes; (void)n_in; (void)out_size;

    // zero scatter targets (agg1 + agg2)
    {
        int total = N_NODES * NHID / 4 + N_NODES * NC_PAD / 4;
        zero_kernel<<<(total + 255) / 256, 256>>>();
    }

    // layer 1 dense: 256 rows per block
    gemm1_kernel<<<(N_NODES + 255) / 256, 256>>>(x, W1);

    // layer 1 sparse aggregate: 10 v4-chunks per edge
    {
        long long total = (long long)N_EDGES * 10;
        int blocks = (int)((total + 255) / 256);
        scatter1_kernel<<<blocks, 256>>>(src, dst, ew);
    }

    // relu + bias + dropout + GEMM2 fused
    mid_kernel<<<(N_NODES + 255) / 256, 256>>>(b1, W2, mask);

    // layer 2 sparse aggregate: 2 v4-chunks per edge
    {
        long long total = (long long)N_EDGES * 2;
        int blocks = (int)((total + 255) / 256);
        scatter2_kernel<<<blocks, 256>>>(src, dst, ew);
    }

    // bias + log_softmax (reads padded agg2, writes 7-wide out)
    logsoftmax_kernel<<<(N_NODES + 255) / 256, 256>>>(b2, out);
}